// round 2
// baseline (speedup 1.0000x reference)
#include <cuda_runtime.h>

// Problem constants (fixed by setup_inputs): b=2, s=4096, h=16, p=n=64, BL=64
#define NB   2
#define NH   16
#define NC   64      // chunks = 4096/64
#define BL   64
#define PAD  68      // row stride in floats: multiple of 4 (float4-aligned rows)

// Scratch (allocation-free rule: __device__ globals)
__device__ float g_states[NB*NH*NC*64*64];   // per-chunk raw states, TRANSPOSED [n][p]
__device__ float g_S[NB*NH*NC*64*64];        // scanned states, TRANSPOSED [n][p]
__device__ float g_ecl[NB*NH*NC*BL];         // exp(cumsum) per position
__device__ float g_tot[NB*NH*NC];            // chunk total of A

// ---------------------------------------------------------------------------
// Pass 1: per (b,h,chunk) tile. cumsum(A), GEMM1 (masked C·B^T), GEMM2
// (Y_diag), GEMM3 (chunk state, transposed). All inner-loop smem reads are
// row-broadcast or tx-contiguous float4 -> conflict-free.
// ---------------------------------------------------------------------------
__global__ void __launch_bounds__(256) pass1_kernel(
    const float* __restrict__ X, const float* __restrict__ A,
    const float* __restrict__ B, const float* __restrict__ C,
    float* __restrict__ Y)
{
    extern __shared__ float sm[];
    float* Xs = sm;                // [64][PAD]  X row-major
    float* Cs = sm + 64*PAD;       // [64][PAD]  C row-major, reused as G
    float* Bt = sm + 2*64*PAD;     // [64][PAD]  B TRANSPOSED: Bt[n][s]
    __shared__ float s_a[64], s_cs[64], s_ecl[64], s_em[64], s_w[64];

    const int c = blockIdx.x, h = blockIdx.y, b = blockIdx.z;
    const int bhc = (b*NH + h)*NC + c;
    const int tid = threadIdx.x;
    const size_t base = ((size_t)((b*4096 + c*BL)*NH + h))*64;

    if (tid < 64) s_a[tid] = A[(size_t)(b*4096 + c*BL + tid)*NH + h];

    // Cooperative loads: X,C straight; B transposed via scalar STS
    const int r0 = tid >> 4;
    const int c4 = (tid & 15) << 2;
    #pragma unroll
    for (int i = 0; i < 4; i++) {
        const int row = r0 + i*16;
        const size_t g = base + (size_t)row*1024 + c4;
        *(float4*)(Xs + row*PAD + c4) = *(const float4*)(X + g);
        *(float4*)(Cs + row*PAD + c4) = *(const float4*)(C + g);
        float4 bv = *(const float4*)(B + g);
        Bt[(c4+0)*PAD + row] = bv.x;
        Bt[(c4+1)*PAD + row] = bv.y;
        Bt[(c4+2)*PAD + row] = bv.z;
        Bt[(c4+3)*PAD + row] = bv.w;
    }
    __syncthreads();

    // Inclusive cumsum of A over 64 positions
    if (tid < 64) {
        float v = s_a[tid];
        #pragma unroll
        for (int o = 1; o < 32; o <<= 1) {
            float t = __shfl_up_sync(0xffffffffu, v, o);
            if ((tid & 31) >= o) v += t;
        }
        s_cs[tid] = v;
    }
    __syncthreads();
    if (tid >= 32 && tid < 64) s_cs[tid] += s_cs[31];
    __syncthreads();
    if (tid < 64) {
        const float csl   = s_cs[tid];
        const float total = s_cs[63];
        const float ecl   = expf(csl);
        s_ecl[tid] = ecl;                       // exp(cs[l])
        s_em[tid]  = expf(s_a[tid] - csl);      // exp(A[s]-cs[s])
        s_w[tid]   = expf(total - csl);         // decay_states
        g_ecl[bhc*64 + tid] = ecl;
        if (tid == 63) g_tot[bhc] = csl;
    }
    __syncthreads();

    const int tx = tid & 15, ty = tid >> 4;
    const int lr = ty << 2, sc = tx << 2;   // 4x4 micro-tile per thread

    // ---- GEMM 1: G[l][s] = sum_n C[l][n] * Bt[n][s] ----
    float acc[4][4] = {};
    #pragma unroll 4
    for (int n = 0; n < 64; n += 4) {
        float cv[4][4];
        #pragma unroll
        for (int i = 0; i < 4; i++)
            *(float4*)cv[i] = *(const float4*)(Cs + (lr+i)*PAD + n);   // broadcast
        #pragma unroll
        for (int k = 0; k < 4; k++) {
            float bt[4];
            *(float4*)bt = *(const float4*)(Bt + (n+k)*PAD + sc);      // contiguous
            #pragma unroll
            for (int i = 0; i < 4; i++)
                #pragma unroll
                for (int j = 0; j < 4; j++)
                    acc[i][j] += cv[i][k] * bt[j];
        }
    }
    __syncthreads();   // all reads of Cs done -> overwrite with masked G
    #pragma unroll
    for (int i = 0; i < 4; i++) {
        const int l = lr + i;
        const float el = s_ecl[l];
        #pragma unroll
        for (int j = 0; j < 4; j++) {
            const int s = sc + j;
            Cs[l*PAD + s] = (l >= s) ? acc[i][j] * el * s_em[s] : 0.f;
        }
    }
    __syncthreads();

    // ---- GEMM 2: Y_diag[l][p] = sum_s G[l][s] * X[s][p] ----
    float yacc[4][4] = {};
    #pragma unroll 4
    for (int s = 0; s < 64; s += 4) {
        float gv[4][4];
        #pragma unroll
        for (int i = 0; i < 4; i++)
            *(float4*)gv[i] = *(const float4*)(Cs + (lr+i)*PAD + s);   // broadcast
        #pragma unroll
        for (int k = 0; k < 4; k++) {
            float xv[4];
            *(float4*)xv = *(const float4*)(Xs + (s+k)*PAD + sc);      // contiguous
            #pragma unroll
            for (int i = 0; i < 4; i++)
                #pragma unroll
                for (int j = 0; j < 4; j++)
                    yacc[i][j] += gv[i][k] * xv[j];
        }
    }
    #pragma unroll
    for (int i = 0; i < 4; i++)
        *(float4*)(Y + base + (size_t)(lr+i)*1024 + sc) =
            make_float4(yacc[i][0], yacc[i][1], yacc[i][2], yacc[i][3]);

    // ---- GEMM 3 (transposed): St[n][p] = sum_l Bt[n][l] * w[l] * X[l][p] ----
    float sacc[4][4] = {};
    #pragma unroll 4
    for (int l = 0; l < 64; l += 4) {
        float bw[4][4];
        #pragma unroll
        for (int i = 0; i < 4; i++)
            *(float4*)bw[i] = *(const float4*)(Bt + (lr+i)*PAD + l);   // broadcast
        #pragma unroll
        for (int k = 0; k < 4; k++) {
            float xv[4];
            *(float4*)xv = *(const float4*)(Xs + (l+k)*PAD + sc);      // contiguous
            const float wl = s_w[l+k];
            #pragma unroll
            for (int j = 0; j < 4; j++) xv[j] *= wl;
            #pragma unroll
            for (int i = 0; i < 4; i++)
                #pragma unroll
                for (int j = 0; j < 4; j++)
                    sacc[i][j] += bw[i][k] * xv[j];
        }
    }
    float* st = g_states + (size_t)bhc*4096;   // layout [n][p]
    #pragma unroll
    for (int i = 0; i < 4; i++)
        *(float4*)(st + (lr+i)*64 + sc) =
            make_float4(sacc[i][0], sacc[i][1], sacc[i][2], sacc[i][3]);
}

// ---------------------------------------------------------------------------
// Pass 2: inter-chunk scan per (b,h). S_{c+1} = exp(tot_c)*(S_c + state_c).
// Elementwise in the 64x64 state -> layout-agnostic. 16 floats/thread in regs.
// ---------------------------------------------------------------------------
__global__ void __launch_bounds__(256) pass2_kernel()
{
    const int bh  = blockIdx.x;
    const int tid = threadIdx.x;
    const float4* st = (const float4*)(g_states + (size_t)bh*NC*4096);
    float4*       so = (float4*)(g_S + (size_t)bh*NC*4096);
    float4 S[4];
    #pragma unroll
    for (int k = 0; k < 4; k++) S[k] = make_float4(0.f, 0.f, 0.f, 0.f);

    for (int c = 0; c < NC; c++) {
        const float e = expf(g_tot[bh*NC + c]);
        const int o = c*1024 + tid;
        #pragma unroll
        for (int k = 0; k < 4; k++) {
            float4 v = st[o + k*256];
            so[o + k*256] = S[k];             // state BEFORE absorbing chunk c
            S[k].x = e * (S[k].x + v.x);
            S[k].y = e * (S[k].y + v.y);
            S[k].z = e * (S[k].z + v.z);
            S[k].w = e * (S[k].w + v.w);
        }
    }
}

// ---------------------------------------------------------------------------
// Pass 3: Y[l][p] += exp(cs[l]) * sum_n C[l][n] * St[n][p]
// ---------------------------------------------------------------------------
__global__ void __launch_bounds__(256) pass3_kernel(
    const float* __restrict__ C, float* __restrict__ Y)
{
    __shared__ float Cs[64*PAD];   // C row-major [l][n]
    __shared__ float Ss[64*PAD];   // S transposed [n][p] (as stored)
    __shared__ float s_ecl[64];

    const int c = blockIdx.x, h = blockIdx.y, b = blockIdx.z;
    const int bhc = (b*NH + h)*NC + c;
    const int tid = threadIdx.x;
    const size_t base = ((size_t)((b*4096 + c*BL)*NH + h))*64;
    const float* Sg = g_S + (size_t)bhc*4096;

    const int r0 = tid >> 4;
    const int c4 = (tid & 15) << 2;
    #pragma unroll
    for (int i = 0; i < 4; i++) {
        const int row = r0 + i*16;
        *(float4*)(Cs + row*PAD + c4) = *(const float4*)(C + base + (size_t)row*1024 + c4);
        *(float4*)(Ss + row*PAD + c4) = *(const float4*)(Sg + row*64 + c4);
    }
    if (tid < 64) s_ecl[tid] = g_ecl[bhc*64 + tid];
    __syncthreads();

    const int tx = tid & 15, ty = tid >> 4;
    const int lr = ty << 2, pc = tx << 2;
    float acc[4][4] = {};
    #pragma unroll 4
    for (int n = 0; n < 64; n += 4) {
        float cv[4][4];
        #pragma unroll
        for (int i = 0; i < 4; i++)
            *(float4*)cv[i] = *(const float4*)(Cs + (lr+i)*PAD + n);   // broadcast
        #pragma unroll
        for (int k = 0; k < 4; k++) {
            float sv[4];
            *(float4*)sv = *(const float4*)(Ss + (n+k)*PAD + pc);      // contiguous
            #pragma unroll
            for (int i = 0; i < 4; i++)
                #pragma unroll
                for (int j = 0; j < 4; j++)
                    acc[i][j] += cv[i][k] * sv[j];
        }
    }
    #pragma unroll
    for (int i = 0; i < 4; i++) {
        const float el = s_ecl[lr + i];
        float* yp = Y + base + (size_t)(lr+i)*1024 + pc;
        float4 y = *(float4*)yp;
        y.x += el * acc[i][0];
        y.y += el * acc[i][1];
        y.z += el * acc[i][2];
        y.w += el * acc[i][3];
        *(float4*)yp = y;
    }
}

// ---------------------------------------------------------------------------
extern "C" void kernel_launch(void* const* d_in, const int* in_sizes, int n_in,
                              void* d_out, int out_size)
{
    const float* X = (const float*)d_in[0];
    const float* A = (const float*)d_in[1];
    const float* B = (const float*)d_in[2];
    const float* C = (const float*)d_in[3];
    float* Y = (float*)d_out;

    const int smem1 = 3 * 64 * PAD * sizeof(float);   // 52,224 B > 48K -> opt-in
    cudaFuncSetAttribute(pass1_kernel,
                         cudaFuncAttributeMaxDynamicSharedMemorySize, smem1);

    dim3 grid(NC, NH, NB);
    pass1_kernel<<<grid, 256, smem1>>>(X, A, B, C, Y);
    pass2_kernel<<<32, 256>>>();
    pass3_kernel<<<grid, 256>>>(C, Y);
}